// round 14
// baseline (speedup 1.0000x reference)
#include <cuda_runtime.h>
#include <cuda_fp16.h>

#define N_NODES 50000
#define N_EDGES 800000
#define NFEAT   512
#define NHID    96
#define NCLASS  40

#define SCAN_BLOCKS ((N_NODES + 1023) / 1024)   // 49

// ---------------- scratch (device globals; zero-initialized at load) ---------
__device__ __half g_support_h[N_NODES * NHID];        // fp16(x @ W1 + b1)
__device__ __half g_h_h[N_NODES * NHID];              // fp16(relu(agg))
__device__ int    g_deg[N_NODES];                     // zeroed at load AND at end of k3c
__device__ int    g_off[N_NODES + 1];
__device__ int    g_cur[N_NODES];
__device__ int    g_bsum[SCAN_BLOCKS];
__device__ unsigned long long g_epak[N_EDGES];        // {src, wt} packed

// ---------------- streams/events (created once at load; NOT device memory) ---
static cudaStream_t g_s2;
static cudaEvent_t  g_ev_fork, g_ev_join;
static struct StreamInit {
    StreamInit() {
        cudaStreamCreateWithFlags(&g_s2, cudaStreamNonBlocking);
        cudaEventCreateWithFlags(&g_ev_fork, cudaEventDisableTiming);
        cudaEventCreateWithFlags(&g_ev_join, cudaEventDisableTiming);
    }
} g_stream_init;

// ---------------- helpers ----------------------------------------------------
__device__ __forceinline__ unsigned cvt_tf32(float f) {
    unsigned u;
    asm("cvt.rna.tf32.f32 %0, %1;" : "=r"(u) : "f"(f));
    return u;
}

__device__ __forceinline__ void mma_tf32(float c[4], const unsigned a[4],
                                         unsigned b0, unsigned b1) {
    asm volatile(
        "mma.sync.aligned.m16n8k8.row.col.f32.tf32.tf32.f32 "
        "{%0,%1,%2,%3}, {%4,%5,%6,%7}, {%8,%9}, {%0,%1,%2,%3};"
        : "+f"(c[0]), "+f"(c[1]), "+f"(c[2]), "+f"(c[3])
        : "r"(a[0]), "r"(a[1]), "r"(a[2]), "r"(a[3]), "r"(b0), "r"(b1));
}

// Deterministic per-block probe: int64 edge_index (values < 2^31, LE) has all
// odd 32-bit words zero; int32 edge_index has random node ids there.
__device__ __forceinline__ int probe_is64(const int* __restrict__ ei32) {
    int all_zero = 1;
#pragma unroll
    for (int j = 1; j < 16; j += 2) all_zero &= (ei32[j] == 0);
    return all_zero;
}

__device__ __forceinline__ int load_idx(const void* ei, int pos, int is64) {
    if (is64) return (int)((const long long*)ei)[pos];
    return ((const int*)ei)[pos];
}

// ---------------- K1: support = fp16(x @ W1 + b1), TF32 tensor cores ---------
// Block: 128 threads / 4 warps, tile 128 rows x 96 cols, k-tile 32.
// Each warp computes 32 rows; B fragments reused across both 16-row groups.
__global__ __launch_bounds__(128)
void k1_gemm1_tc(const float* __restrict__ x, const float* __restrict__ W1,
                 const float* __restrict__ b1) {
    __shared__ __align__(16) unsigned Xs[128][36];
    __shared__ __align__(16) unsigned Ws[32][104];

    const int tid  = threadIdx.x;
    const int warp = tid >> 5;
    const int lane = tid & 31;
    const int g    = lane >> 2;
    const int tg   = lane & 3;
    const int row0 = blockIdx.x * 128;
    const int rw   = warp * 32;

    float c[2][12][4];
#pragma unroll
    for (int gr = 0; gr < 2; gr++)
#pragma unroll
        for (int j = 0; j < 12; j++)
#pragma unroll
            for (int q = 0; q < 4; q++) c[gr][j][q] = 0.0f;

    for (int kt = 0; kt < NFEAT; kt += 32) {
#pragma unroll
        for (int t = 0; t < 8; t++) {
            int fidx = (tid + t * 128) * 4;
            int r = fidx >> 5, k = fidx & 31;
            int row = row0 + r;
            float4 v = make_float4(0.f, 0.f, 0.f, 0.f);
            if (row < N_NODES) v = *(const float4*)&x[row * NFEAT + kt + k];
            uint4 u;
            u.x = cvt_tf32(v.x); u.y = cvt_tf32(v.y);
            u.z = cvt_tf32(v.z); u.w = cvt_tf32(v.w);
            *(uint4*)&Xs[r][k] = u;
        }
#pragma unroll
        for (int t = 0; t < 6; t++) {
            int fidx = (tid + t * 128) * 4;
            int k = fidx / 96, cc = fidx % 96;
            float4 v = *(const float4*)&W1[(kt + k) * NHID + cc];
            uint4 u;
            u.x = cvt_tf32(v.x); u.y = cvt_tf32(v.y);
            u.z = cvt_tf32(v.z); u.w = cvt_tf32(v.w);
            *(uint4*)&Ws[k][cc] = u;
        }
        __syncthreads();

#pragma unroll
        for (int k8 = 0; k8 < 4; k8++) {
            const int k0 = k8 * 8;
            unsigned a0[4], a1[4];
            a0[0] = Xs[rw + g][k0 + tg];
            a0[1] = Xs[rw + g + 8][k0 + tg];
            a0[2] = Xs[rw + g][k0 + tg + 4];
            a0[3] = Xs[rw + g + 8][k0 + tg + 4];
            a1[0] = Xs[rw + 16 + g][k0 + tg];
            a1[1] = Xs[rw + 16 + g + 8][k0 + tg];
            a1[2] = Xs[rw + 16 + g][k0 + tg + 4];
            a1[3] = Xs[rw + 16 + g + 8][k0 + tg + 4];
#pragma unroll
            for (int j = 0; j < 12; j++) {
                unsigned b0 = Ws[k0 + tg][j * 8 + g];
                unsigned b1 = Ws[k0 + tg + 4][j * 8 + g];
                mma_tf32(c[0][j], a0, b0, b1);
                mma_tf32(c[1][j], a1, b0, b1);
            }
        }
        __syncthreads();
    }

#pragma unroll
    for (int gr = 0; gr < 2; gr++) {
#pragma unroll
        for (int j = 0; j < 12; j++) {
            const int col = j * 8 + tg * 2;
            const float bb0 = __ldg(&b1[col]);
            const float bb1 = __ldg(&b1[col + 1]);
            int r0g = row0 + rw + gr * 16 + g;
            if (r0g < N_NODES) {
                __half2 h = __floats2half2_rn(c[gr][j][0] + bb0, c[gr][j][1] + bb1);
                *(__half2*)&g_support_h[r0g * NHID + col] = h;
            }
            int r1g = r0g + 8;
            if (r1g < N_NODES) {
                __half2 h = __floats2half2_rn(c[gr][j][2] + bb0, c[gr][j][3] + bb1);
                *(__half2*)&g_support_h[r1g * NHID + col] = h;
            }
        }
    }
}

// ---------------- K2: degree histogram over dst (one edge/thread) ------------
// g_deg is guaranteed zero on entry (module-load init on first call; re-zeroed
// by k3c at the end of every previous pipeline run).
__global__ void k2_hist(const void* __restrict__ ei) {
    __shared__ int s_is64;
    if (threadIdx.x == 0) s_is64 = probe_is64((const int*)ei);
    __syncthreads();
    int e = blockIdx.x * blockDim.x + threadIdx.x;
    if (e < N_EDGES) {
        int dst = load_idx(ei, N_EDGES + e, s_is64);
        atomicAdd(&g_deg[dst], 1);
    }
}

// ---------------- K3a: per-block scan (49 blocks x 1024) ---------------------
__global__ __launch_bounds__(1024)
void k3a_block_scan() {
    __shared__ int wsum[32];
    const int tid  = threadIdx.x;
    const int lane = tid & 31;
    const int wid  = tid >> 5;
    const int i    = blockIdx.x * 1024 + tid;

    int v = (i < N_NODES) ? g_deg[i] : 0;
    int s = v;
#pragma unroll
    for (int d = 1; d < 32; d <<= 1) {
        int t = __shfl_up_sync(0xffffffffu, s, d);
        if (lane >= d) s += t;
    }
    if (lane == 31) wsum[wid] = s;
    __syncthreads();
    if (wid == 0) {
        int ws = wsum[lane];
#pragma unroll
        for (int d = 1; d < 32; d <<= 1) {
            int t = __shfl_up_sync(0xffffffffu, ws, d);
            if (lane >= d) ws += t;
        }
        wsum[lane] = ws;
    }
    __syncthreads();
    int excl = (wid ? wsum[wid - 1] : 0) + s - v;
    if (i < N_NODES) g_off[i] = excl;
    if (tid == 1023) g_bsum[blockIdx.x] = wsum[31];
}

// ---------------- K3c: add block prefix + re-zero g_deg for next run ---------
__global__ __launch_bounds__(256)
void k3c_add_offsets() {
    __shared__ int svals[64];
    __shared__ int prefix;
    const int tid = threadIdx.x;
    const int b   = blockIdx.x >> 2;

    if (tid < 64) svals[tid] = (tid < b && tid < SCAN_BLOCKS) ? g_bsum[tid] : 0;
    __syncthreads();
    if (tid == 0) {
        int acc = 0;
#pragma unroll
        for (int j = 0; j < 64; j++) acc += svals[j];
        prefix = acc;
    }
    __syncthreads();

    int i = blockIdx.x * 256 + tid;
    if (i < N_NODES) {
        int off = g_off[i] + prefix;
        g_off[i] = off;
        g_cur[i] = off;
        g_deg[i] = 0;                 // leave zeroed for next graph replay
    }
    if (i == 0) g_off[N_NODES] = N_EDGES;
}

// ---------------- K4: scatter edges into CSR buckets (one edge/thread) -------
__global__ void k4_scatter(const void* __restrict__ ei,
                           const float* __restrict__ ew) {
    __shared__ int s_is64;
    if (threadIdx.x == 0) s_is64 = probe_is64((const int*)ei);
    __syncthreads();
    int e = blockIdx.x * blockDim.x + threadIdx.x;
    if (e < N_EDGES) {
        int is64 = s_is64;
        int src = load_idx(ei, e, is64);
        int dst = load_idx(ei, N_EDGES + e, is64);
        int pos = atomicAdd(&g_cur[dst], 1);
        g_epak[pos] = (unsigned long long)(unsigned)src |
                      ((unsigned long long)__float_as_uint(ew[e]) << 32);
    }
}

// ---------------- K5: aggregate + relu (warp per node, dual-edge unroll) -----
__global__ __launch_bounds__(256)
void k5_aggregate() {
    const int warp = threadIdx.x >> 5;
    const int lane = threadIdx.x & 31;
    const int n    = blockIdx.x * 8 + warp;
    if (n >= N_NODES) return;

    const int s = g_off[n];
    const int e = g_off[n + 1];
    float a0x = 0.f, a0y = 0.f, a1x = 0.f, a1y = 0.f;

    int i = s;
    for (; i + 2 <= e; i += 2) {
        unsigned long long p0 = g_epak[i];
        unsigned long long p1 = g_epak[i + 1];
        int   s0 = (int)(unsigned)(p0 & 0xffffffffull);
        int   s1 = (int)(unsigned)(p1 & 0xffffffffull);
        float w0 = __uint_as_float((unsigned)(p0 >> 32));
        float w1 = __uint_as_float((unsigned)(p1 >> 32));
        const __half2* r0 = (const __half2*)(g_support_h + s0 * NHID);
        const __half2* r1 = (const __half2*)(g_support_h + s1 * NHID);
        float2 f00 = __half22float2(r0[lane]);
        float2 f10 = __half22float2(r1[lane]);
        a0x += f00.x * w0 + f10.x * w1;
        a0y += f00.y * w0 + f10.y * w1;
        if (lane < 16) {
            float2 f01 = __half22float2(r0[32 + lane]);
            float2 f11 = __half22float2(r1[32 + lane]);
            a1x += f01.x * w0 + f11.x * w1;
            a1y += f01.y * w0 + f11.y * w1;
        }
    }
    if (i < e) {
        unsigned long long p = g_epak[i];
        int   src = (int)(unsigned)(p & 0xffffffffull);
        float w   = __uint_as_float((unsigned)(p >> 32));
        const __half2* rp = (const __half2*)(g_support_h + src * NHID);
        float2 f0 = __half22float2(rp[lane]);
        a0x += f0.x * w;
        a0y += f0.y * w;
        if (lane < 16) {
            float2 f1 = __half22float2(rp[32 + lane]);
            a1x += f1.x * w;
            a1y += f1.y * w;
        }
    }

    __half2* hp = (__half2*)(g_h_h + n * NHID);
    hp[lane] = __floats2half2_rn(fmaxf(a0x, 0.f), fmaxf(a0y, 0.f));
    if (lane < 16)
        hp[32 + lane] = __floats2half2_rn(fmaxf(a1x, 0.f), fmaxf(a1y, 0.f));
}

// ---------------- K6: logits = h @ W2 + b2, then log_softmax -----------------
__global__ __launch_bounds__(320)
void k6_gemm2_softmax(const float* __restrict__ W2, const float* __restrict__ b2,
                      float* __restrict__ out) {
    __shared__ __align__(16) float Hs[NHID][68];
    __shared__ float W2s[NHID][NCLASS];
    __shared__ float ms[64], ls[64];

    const int tid   = threadIdx.y * 40 + threadIdx.x;
    const int node0 = blockIdx.x * 64;

    for (int idx = tid; idx < NHID * NCLASS; idx += 320)
        W2s[idx / NCLASS][idx % NCLASS] = W2[idx];
    for (int idx = tid; idx < 64 * (NHID / 2); idx += 320) {
        int n  = idx / (NHID / 2);
        int kk = idx % (NHID / 2);
        int node = node0 + n;
        float2 f = make_float2(0.f, 0.f);
        if (node < N_NODES)
            f = __half22float2(*(const __half2*)&g_h_h[node * NHID + 2 * kk]);
        Hs[2 * kk][n]     = f.x;
        Hs[2 * kk + 1][n] = f.y;
    }
    __syncthreads();

    const int c     = threadIdx.x;
    const int nbase = threadIdx.y * 8;
    float bb = b2[c];
    float acc[8];
#pragma unroll
    for (int j = 0; j < 8; j++) acc[j] = bb;

#pragma unroll 4
    for (int k = 0; k < NHID; k++) {
        float  w  = W2s[k][c];
        float4 h0 = *(const float4*)(&Hs[k][nbase]);
        float4 h1 = *(const float4*)(&Hs[k][nbase + 4]);
        acc[0] += h0.x * w; acc[1] += h0.y * w;
        acc[2] += h0.z * w; acc[3] += h0.w * w;
        acc[4] += h1.x * w; acc[5] += h1.y * w;
        acc[6] += h1.z * w; acc[7] += h1.w * w;
    }
    __syncthreads();

    float* Ls = &Hs[0][0];
#pragma unroll
    for (int j = 0; j < 8; j++) Ls[(nbase + j) * NCLASS + c] = acc[j];
    __syncthreads();

    if (tid < 64) {
        float m = -1e30f;
        for (int cc = 0; cc < NCLASS; cc++) m = fmaxf(m, Ls[tid * NCLASS + cc]);
        float ssum = 0.0f;
        for (int cc = 0; cc < NCLASS; cc++) ssum += expf(Ls[tid * NCLASS + cc] - m);
        ms[tid] = m;
        ls[tid] = logf(ssum);
    }
    __syncthreads();

    for (int idx = tid; idx < 64 * NCLASS; idx += 320) {
        int n    = idx / NCLASS;
        int node = node0 + n;
        if (node < N_NODES)
            out[node * NCLASS + (idx % NCLASS)] = Ls[idx] - ms[n] - ls[n];
    }
}

// ---------------- launch ------------------------------------------------------
extern "C" void kernel_launch(void* const* d_in, const int* in_sizes, int n_in,
                              void* d_out, int out_size) {
    const float* x  = (const float*)d_in[0];
    const void*  ei = d_in[1];
    const float* ew = (const float*)d_in[2];
    const float* W1 = (const float*)d_in[3];
    const float* b1 = (const float*)d_in[4];
    const float* W2 = (const float*)d_in[5];
    const float* b2 = (const float*)d_in[6];
    float* out = (float*)d_out;

    // Fork: CSR build (side stream) || dense GEMM (main stream).
    cudaEventRecord(g_ev_fork, 0);
    cudaStreamWaitEvent(g_s2, g_ev_fork, 0);

    // side stream: CSR pipeline (4 kernels; g_deg pre-zeroed by prior run)
    k2_hist<<<(N_EDGES + 255) / 256, 256, 0, g_s2>>>(ei);
    k3a_block_scan<<<SCAN_BLOCKS, 1024, 0, g_s2>>>();
    k3c_add_offsets<<<(N_NODES + 255) / 256, 256, 0, g_s2>>>();
    k4_scatter<<<(N_EDGES + 255) / 256, 256, 0, g_s2>>>(ei, ew);

    // main stream: dense transform
    k1_gemm1_tc<<<(N_NODES + 127) / 128, 128>>>(x, W1, b1);

    // Join
    cudaEventRecord(g_ev_join, g_s2);
    cudaStreamWaitEvent(0, g_ev_join, 0);

    k5_aggregate<<<(N_NODES + 7) / 8, 256>>>();
    k6_gemm2_softmax<<<(N_NODES + 63) / 64, dim3(40, 8)>>>(W2, b2, out);
}